// round 3
// baseline (speedup 1.0000x reference)
#include <cuda_runtime.h>
#include <math.h>
#include <float.h>

// ---------------------------------------------------------------------------
// MSEObserver, fully fused single persistent kernel (128 CTAs, all resident).
//   N*MSE(cand) = sum_j [ C_j*(j*s)^2 - 2*(j*s)*S_j ] + const
// Phases separated by software grid barriers:
//   0: zero histogram + per-block min/max partials
//   1: packed histogram (u64 = count<<42 | biased fix26 sum), RED.64 per elem
//   2: per-chunk (4096-bin) inclusive scan
//   3: redundant per-block chunk-total scan (smem) + candidate eval + select
// All global accumulation is integer => deterministic across graph replays.
// ---------------------------------------------------------------------------

#define NBINS    524288       // 2^19
#define CHUNK    4096
#define NCHUNK   128          // NBINS / CHUNK
#define NB       128          // grid blocks (<=148 SMs -> all resident)
#define NT       1024
#define NCAND    1600
#define MASK42   ((1ull << 42) - 1ull)
#define FIXINV   (1.0 / 67108864.0)

__device__ unsigned long long g_hist[NBINS];
__device__ unsigned int       g_cntS[NBINS];    // inclusive scan within chunk
__device__ long long          g_sumS[NBINS];
__device__ unsigned int       g_cntCr[NCHUNK];  // raw chunk totals
__device__ long long          g_sumCr[NCHUNK];
__device__ float              g_pmin[NB];
__device__ float              g_pmax[NB];
__device__ double             g_score[NCAND];
__device__ float              g_bmin[NCAND];
__device__ float              g_bmax[NCAND];
__device__ unsigned int       g_done;
__device__ unsigned int       g_barcnt[3];      // arrive counters (self-reset)
__device__ unsigned int       g_barrel[3];      // release counters (monotone)

// Sense-versioned grid barrier; safe across graph replays (snapshot compare).
__device__ __forceinline__ void grid_bar(int id) {
    __syncthreads();
    if (threadIdx.x == 0) {
        unsigned int snap = *((volatile unsigned int*)&g_barrel[id]);
        __threadfence();
        unsigned int v = atomicAdd(&g_barcnt[id], 1u);
        if (v == NB - 1u) {
            g_barcnt[id] = 0u;                 // reset for next launch
            __threadfence();
            atomicAdd(&g_barrel[id], 1u);      // release
        } else {
            while (*((volatile unsigned int*)&g_barrel[id]) == snap)
                __nanosleep(32);
        }
        __threadfence();
    }
    __syncthreads();
}

__device__ __forceinline__ void hist_one(float f, float xmin, float invw) {
    int b = (int)((f - xmin) * invw);
    b = max(0, min((int)(NBINS - 1), b));
    long long fx = llrintf(f * 67108864.0f);   // f*2^26 exact; RN-even to int
    unsigned long long p = (1ull << 42) + (unsigned long long)(fx + 536870912ll);
    atomicAdd(&g_hist[b], p);
}

// ---------------------------------------------------------------------------
__global__ __launch_bounds__(NT, 1) void k_all(const float* __restrict__ x,
                                               int n, float* __restrict__ out) {
    const int t = threadIdx.x, lane = t & 31, w = t >> 5;
    const int gid = blockIdx.x * NT + t;
    const int total = NB * NT;
    const int n4 = n >> 2;
    const float4* x4 = (const float4*)x;

    __shared__ float sred[32], sred2[32];
    __shared__ float s_min, s_max;
    __shared__ unsigned int swc[32];
    __shared__ long long sws[32];
    __shared__ unsigned int s_cc[NCHUNK];
    __shared__ long long    s_cs[NCHUNK];

    // ---------------- Phase 0: zero hist + minmax partials ----------------
    for (int i = gid; i < NBINS; i += total) g_hist[i] = 0ull;

    {
        float m = FLT_MAX, M = -FLT_MAX;
        for (int i = gid; i < n4; i += total) {
            float4 v = x4[i];
            m = fminf(m, fminf(fminf(v.x, v.y), fminf(v.z, v.w)));
            M = fmaxf(M, fmaxf(fmaxf(v.x, v.y), fmaxf(v.z, v.w)));
        }
        if (gid == 0) {
            for (int i = n4 << 2; i < n; ++i) { m = fminf(m, x[i]); M = fmaxf(M, x[i]); }
        }
        #pragma unroll
        for (int o = 16; o > 0; o >>= 1) {
            m = fminf(m, __shfl_xor_sync(0xFFFFFFFFu, m, o));
            M = fmaxf(M, __shfl_xor_sync(0xFFFFFFFFu, M, o));
        }
        if (lane == 0) { sred[w] = m; sred2[w] = M; }
        __syncthreads();
        if (t == 0) {
            float a = sred[0], b = sred2[0];
            for (int i = 1; i < 32; ++i) { a = fminf(a, sred[i]); b = fmaxf(b, sred2[i]); }
            g_pmin[blockIdx.x] = a;
            g_pmax[blockIdx.x] = b;
        }
    }
    grid_bar(0);

    // ---------------- Phase 1: histogram ----------------
    {
        if (t < 32) {
            float m = FLT_MAX, M = -FLT_MAX;
            for (int i = lane; i < NB; i += 32) {
                m = fminf(m, g_pmin[i]);
                M = fmaxf(M, g_pmax[i]);
            }
            #pragma unroll
            for (int o = 16; o > 0; o >>= 1) {
                m = fminf(m, __shfl_xor_sync(0xFFFFFFFFu, m, o));
                M = fmaxf(M, __shfl_xor_sync(0xFFFFFFFFu, M, o));
            }
            if (lane == 0) { s_min = m; s_max = M; }
        }
        __syncthreads();
        float xmin = s_min, xmax = s_max;
        float invw = (float)NBINS / (xmax - xmin);
        for (int i = gid; i < n4; i += total) {
            float4 v = x4[i];
            hist_one(v.x, xmin, invw);
            hist_one(v.y, xmin, invw);
            hist_one(v.z, xmin, invw);
            hist_one(v.w, xmin, invw);
        }
        if (gid == 0) {
            for (int i = n4 << 2; i < n; ++i) hist_one(x[i], xmin, invw);
        }
    }
    grid_bar(1);

    // ---------------- Phase 2: per-chunk scan (chunk = 4096 bins) --------
    {
        int base = blockIdx.x * CHUNK + t * 4;
        unsigned int c[4]; long long s[4];
        #pragma unroll
        for (int i = 0; i < 4; ++i) {
            unsigned long long p = g_hist[base + i];
            unsigned int cc = (unsigned int)(p >> 42);
            c[i] = cc;
            s[i] = (long long)(p & MASK42) - ((long long)cc << 29);
        }
        // in-thread inclusive
        #pragma unroll
        for (int i = 1; i < 4; ++i) { c[i] += c[i - 1]; s[i] += s[i - 1]; }
        unsigned int tc = c[3]; long long ts = s[3];
        unsigned int ic = tc; long long is = ts;
        #pragma unroll
        for (int off = 1; off < 32; off <<= 1) {
            unsigned int c2 = __shfl_up_sync(0xFFFFFFFFu, ic, off);
            long long s2 = __shfl_up_sync(0xFFFFFFFFu, is, off);
            if (lane >= off) { ic += c2; is += s2; }
        }
        if (lane == 31) { swc[w] = ic; sws[w] = is; }
        __syncthreads();
        if (w == 0) {
            unsigned int cw = swc[lane]; long long sw = sws[lane];
            #pragma unroll
            for (int off = 1; off < 32; off <<= 1) {
                unsigned int c2 = __shfl_up_sync(0xFFFFFFFFu, cw, off);
                long long s2 = __shfl_up_sync(0xFFFFFFFFu, sw, off);
                if (lane >= off) { cw += c2; sw += s2; }
            }
            swc[lane] = cw; sws[lane] = sw;
        }
        __syncthreads();
        unsigned int boffc = (w > 0) ? swc[w - 1] : 0u;
        long long    boffs = (w > 0) ? sws[w - 1] : 0ll;
        unsigned int ex_c = boffc + ic - tc;      // thread exclusive offset
        long long    ex_s = boffs + is - ts;
        #pragma unroll
        for (int i = 0; i < 4; ++i) {
            g_cntS[base + i] = ex_c + c[i];
            g_sumS[base + i] = ex_s + s[i];
        }
        if (t == 0) {                              // block total
            g_cntCr[blockIdx.x] = swc[31];
            g_sumCr[blockIdx.x] = sws[31];
        }
    }
    grid_bar(2);

    // ---------------- Phase 3: chunk prefixes (redundant, per block) ------
    if (t < 32) {
        unsigned int c[4]; long long s[4];
        #pragma unroll
        for (int i = 0; i < 4; ++i) {
            c[i] = g_cntCr[lane * 4 + i];
            s[i] = g_sumCr[lane * 4 + i];
        }
        #pragma unroll
        for (int i = 1; i < 4; ++i) { c[i] += c[i - 1]; s[i] += s[i - 1]; }
        unsigned int ic = c[3]; long long is = s[3];
        #pragma unroll
        for (int off = 1; off < 32; off <<= 1) {
            unsigned int c2 = __shfl_up_sync(0xFFFFFFFFu, ic, off);
            long long s2 = __shfl_up_sync(0xFFFFFFFFu, is, off);
            if (lane >= off) { ic += c2; is += s2; }
        }
        unsigned int ex = ic - c[3]; long long exs = is - s[3];   // lane exclusive
        s_cc[lane * 4 + 0] = ex;
        s_cs[lane * 4 + 0] = exs;
        #pragma unroll
        for (int i = 1; i < 4; ++i) {
            s_cc[lane * 4 + i] = ex + c[i - 1];
            s_cs[lane * 4 + i] = exs + s[i - 1];
        }
    }
    __syncthreads();

    // ---------------- eval: 16 buckets = 16 lanes, 2 cands/warp -----------
    {
        float xmin = s_min, xmax = s_max;
        int gw = w * NB + blockIdx.x;                 // spread warps over blocks
        int c = gw * 2 + (lane >> 4);
        if (c < NCAND) {
            int l = lane & 15;
            float xrange = __fsub_rn(xmax, xmin);
            int ii = (c >> 4) + 1;
            int zi = c & 15;
            float fi = (float)ii, zf = (float)zi;

            // exact replication of reference fp32 candidate-parameter math
            float tmp_max = __fmul_rn(__fdiv_rn(xrange, 100.0f), fi);
            float delta   = __fdiv_rn(tmp_max, 15.0f);
            float nmin    = fmaxf(__fmul_rn(-zf, delta), xmin);
            float nmax    = fminf(__fsub_rn(tmp_max, __fmul_rn(zf, delta)), xmax);
            float min_neg = fminf(nmin, 0.0f);
            float max_pos = fmaxf(nmax, 0.0f);
            float scale   = fmaxf(__fdiv_rn(__fsub_rn(max_pos, min_neg), 15.0f), 1.1920929e-7f);
            float zr      = rintf(__fdiv_rn(min_neg, scale));
            float zpc     = fminf(fmaxf(-zr, 0.0f), 15.0f);
            int zp = (int)zpc;
            int j = -zp + l;

            double s     = (double)scale;
            double xminD = (double)xmin;
            double invwD = (double)NBINS / (double)xrange;

            int bt;
            if (l == 15) {
                bt = NBINS;
            } else {
                double th = ((double)j + 0.5) * s;
                double bf = (th - xminD) * invwD;
                bt = (int)floor(bf);
                bt = max(0, min((int)NBINS, bt));
            }
            unsigned int pc_u = 0u; long long ps_u = 0ll;
            if (bt > 0) {
                int bb = bt - 1;
                int ch = bb >> 12;
                pc_u = s_cc[ch] + g_cntS[bb];
                ps_u = s_cs[ch] + g_sumS[bb];
            }
            unsigned int pc_l = __shfl_up_sync(0xFFFFFFFFu, pc_u, 1);
            long long    ps_l = __shfl_up_sync(0xFFFFFFFFu, ps_u, 1);
            if (l == 0) { pc_l = 0u; ps_l = 0ll; }

            double C = (double)(pc_u - pc_l);
            double S = (double)(ps_u - ps_l) * FIXINV;
            double v = (double)j * s;
            double term = C * v * v - 2.0 * v * S;
            #pragma unroll
            for (int off = 1; off < 16; off <<= 1)
                term += __shfl_xor_sync(0xFFFFFFFFu, term, off);
            if (l == 0) {
                g_score[c] = term;
                g_bmin[c] = nmin;
                g_bmax[c] = nmax;
            }
        }
    }

    // ---------------- select: last-done block, lexicographic-first min ----
    __shared__ bool s_last;
    __threadfence();
    __syncthreads();
    if (t == 0) s_last = (atomicAdd(&g_done, 1u) == NB - 1u);
    __syncthreads();
    if (!s_last) return;
    __threadfence();

    __shared__ double ssc[NT];
    __shared__ int sid[NT];
    double best = 1.0e300;
    int bi = NCAND;
    for (int cc = t; cc < NCAND; cc += NT) {
        double sc = g_score[cc];
        if (sc < best) { best = sc; bi = cc; }   // ascending -> first strict min
    }
    ssc[t] = best; sid[t] = bi;
    __syncthreads();
    for (int o = NT / 2; o > 0; o >>= 1) {
        if (t < o) {
            double s2 = ssc[t + o]; int i2 = sid[t + o];
            if (s2 < ssc[t] || (s2 == ssc[t] && i2 < sid[t])) { ssc[t] = s2; sid[t] = i2; }
        }
        __syncthreads();
    }
    if (t == 0) {
        int b = sid[0];
        out[0] = g_bmin[b];
        out[1] = g_bmax[b];
        g_done = 0u;                 // reset for next graph replay
    }
}

// ---------------------------------------------------------------------------
extern "C" void kernel_launch(void* const* d_in, const int* in_sizes, int n_in,
                              void* d_out, int out_size) {
    const float* x = (const float*)d_in[0];
    int n = in_sizes[0];
    k_all<<<NB, NT>>>(x, n, (float*)d_out);
}